// round 2
// baseline (speedup 1.0000x reference)
#include <cuda_runtime.h>
#include <cstdint>

#define SDIM 2048
#define BATCH 2
#define HEADS 16
#define HDIM 64
#define BM 64
#define BN 64
#define TSTR 68   // shared row stride in floats (keeps 16B alignment, breaks bank conflicts)

typedef unsigned long long ull;

// ---- packed f32x2 helpers (sm_100+ fma.rn.f32x2) ----
__device__ __forceinline__ ull pk2(float lo, float hi) {
    ull r;
    asm("mov.b64 %0, {%1, %2};" : "=l"(r)
        : "r"(__float_as_uint(lo)), "r"(__float_as_uint(hi)));
    return r;
}
__device__ __forceinline__ void upk2(ull x, float& lo, float& hi) {
    unsigned int a, b;
    asm("mov.b64 {%0, %1}, %2;" : "=r"(a), "=r"(b) : "l"(x));
    lo = __uint_as_float(a); hi = __uint_as_float(b);
}
__device__ __forceinline__ ull fma2(ull a, ull b, ull c) {
    ull d; asm("fma.rn.f32x2 %0, %1, %2, %3;" : "=l"(d) : "l"(a), "l"(b), "l"(c)); return d;
}
__device__ __forceinline__ ull mul2(ull a, ull b) {
    ull d; asm("mul.rn.f32x2 %0, %1, %2;" : "=l"(d) : "l"(a), "l"(b)); return d;
}

// mask layout flag: 1 = word-per-element (int32 OR float32; masked <=> word != 0)
//                   0 = byte-per-element (uint8/int8; masked <=> byte != 0)
__device__ int g_mask_word_mode;

__global__ void detect_mask_kernel(const unsigned int* m) {
    int word_mode = 1;
    for (int i = 0; i < 1024; i++) {
        const unsigned int w = m[i];
        if (w != 0u && w != 1u && w != 0x3F800000u) { word_mode = 0; break; }
    }
    g_mask_word_mode = word_mode;
}

__global__ __launch_bounds__(256, 2)
void attn_kernel(const float* __restrict__ qg, const float* __restrict__ kg,
                 const float* __restrict__ vg, const float* __restrict__ biasg,
                 const unsigned char* __restrict__ maskg, float* __restrict__ outg)
{
    extern __shared__ float sm[];
    float* Qs = sm;                 // [BM][TSTR]  q rows (pre-scaled by sqrt(D))
    float* Kt = sm + BM * TSTR;     // [HDIM][TSTR] transposed: Kt[d][n]
    float* Vs = sm + 2 * BM * TSTR; // [BN][TSTR]  Vs[n][d]
    float* Ps = sm + 3 * BM * TSTR; // [BM][TSTR]  softmax numerators

    const int tid = threadIdx.x;
    const int m0  = blockIdx.x * BM;
    const int h   = blockIdx.y;
    const int b   = blockIdx.z;
    const int tm  = tid >> 4;   // 0..15 : owns 4 query rows  tm*4..tm*4+3
    const int tn  = tid & 15;   // 0..15 : owns 4 cols (keys in QK phase, d in PV phase)
    const int word_mode = g_mask_word_mode;

    // ---- load Q tile once, scaled by sqrt(D)=8 ----
    for (int idx = tid; idx < BM * 16; idx += 256) {
        const int r = idx >> 4, d4 = (idx & 15) << 2;
        float4 t = *(const float4*)(qg + (((size_t)b * SDIM + (m0 + r)) * HEADS + h) * HDIM + d4);
        t.x *= 8.0f; t.y *= 8.0f; t.z *= 8.0f; t.w *= 8.0f;
        *(float4*)(Qs + r * TSTR + d4) = t;
    }

    ull   o2[4][2] = {{0ull,0ull},{0ull,0ull},{0ull,0ull},{0ull,0ull}};
    float mrow[4]  = {-1e30f, -1e30f, -1e30f, -1e30f};
    float lrow[4]  = {0.f, 0.f, 0.f, 0.f};

    for (int n0 = 0; n0 < SDIM; n0 += BN) {
        __syncthreads();  // previous tile's P/V reads complete before overwrite
        // ---- load K (transposed into Kt[d][n]) and V (natural) ----
        for (int idx = tid; idx < BN * 16; idx += 256) {
            const int r = idx >> 4, d4 = (idx & 15) << 2;
            const size_t base = (((size_t)b * SDIM + (n0 + r)) * HEADS + h) * HDIM + d4;
            const float4 kv = *(const float4*)(kg + base);
            Kt[(d4 + 0) * TSTR + r] = kv.x;
            Kt[(d4 + 1) * TSTR + r] = kv.y;
            Kt[(d4 + 2) * TSTR + r] = kv.z;
            Kt[(d4 + 3) * TSTR + r] = kv.w;
            *(float4*)(Vs + r * TSTR + d4) = *(const float4*)(vg + base);
        }
        __syncthreads();

        // ---- QK^T: c[i][j] = sum_d Qs[row_i][d] * Kt[d][col_j]  (packed f32x2 over j) ----
        ull c2[4][2] = {{0ull,0ull},{0ull,0ull},{0ull,0ull},{0ull,0ull}};
        #pragma unroll 4
        for (int kk0 = 0; kk0 < HDIM; kk0 += 4) {
            float4 qa[4];
            #pragma unroll
            for (int i = 0; i < 4; i++)
                qa[i] = *(const float4*)(Qs + (tm * 4 + i) * TSTR + kk0);
            #pragma unroll
            for (int t = 0; t < 4; t++) {
                const ulonglong2 kv = *(const ulonglong2*)(Kt + (kk0 + t) * TSTR + tn * 4);
                #pragma unroll
                for (int i = 0; i < 4; i++) {
                    const float a = (t == 0) ? qa[i].x : (t == 1) ? qa[i].y
                                  : (t == 2) ? qa[i].z : qa[i].w;
                    const ull a2 = pk2(a, a);
                    c2[i][0] = fma2(a2, kv.x, c2[i][0]);
                    c2[i][1] = fma2(a2, kv.y, c2[i][1]);
                }
            }
        }

        // ---- bias + mask (masked score := exactly 0, still participates in softmax) ----
        float s[4][4];
        #pragma unroll
        for (int i = 0; i < 4; i++) {
            upk2(c2[i][0], s[i][0], s[i][1]);
            upk2(c2[i][1], s[i][2], s[i][3]);
            const int row = m0 + tm * 4 + i;
            const float4 bv = *(const float4*)(biasg +
                (((size_t)b * HEADS + h) * SDIM + row) * SDIM + n0 + tn * 4);
            const size_t melem = ((size_t)b * SDIM + row) * SDIM + n0 + tn * 4;
            int mk0, mk1, mk2, mk3;
            if (word_mode) {
                const int4 mw = *(const int4*)((const int*)maskg + melem);
                mk0 = (mw.x != 0); mk1 = (mw.y != 0); mk2 = (mw.z != 0); mk3 = (mw.w != 0);
            } else {
                const unsigned int mb = *(const unsigned int*)(maskg + melem);
                mk0 = (mb & 0x000000ffu) != 0; mk1 = (mb & 0x0000ff00u) != 0;
                mk2 = (mb & 0x00ff0000u) != 0; mk3 = (mb & 0xff000000u) != 0;
            }
            s[i][0] = mk0 ? 0.f : s[i][0] + bv.x;
            s[i][1] = mk1 ? 0.f : s[i][1] + bv.y;
            s[i][2] = mk2 ? 0.f : s[i][2] + bv.z;
            s[i][3] = mk3 ? 0.f : s[i][3] + bv.w;
        }

        // ---- online softmax (row state shared by the 16 lanes of each row group) ----
        #pragma unroll
        for (int i = 0; i < 4; i++) {
            float tmax = fmaxf(fmaxf(s[i][0], s[i][1]), fmaxf(s[i][2], s[i][3]));
            #pragma unroll
            for (int off = 8; off; off >>= 1)
                tmax = fmaxf(tmax, __shfl_xor_sync(0xffffffffu, tmax, off, 16));
            const float mnew = fmaxf(mrow[i], tmax);
            const float corr = __expf(mrow[i] - mnew);
            mrow[i] = mnew;
            const float p0 = __expf(s[i][0] - mnew), p1 = __expf(s[i][1] - mnew);
            const float p2 = __expf(s[i][2] - mnew), p3 = __expf(s[i][3] - mnew);
            float rs = (p0 + p1) + (p2 + p3);
            #pragma unroll
            for (int off = 8; off; off >>= 1)
                rs += __shfl_xor_sync(0xffffffffu, rs, off, 16);
            lrow[i] = lrow[i] * corr + rs;
            const ull corr2 = pk2(corr, corr);
            o2[i][0] = mul2(o2[i][0], corr2);
            o2[i][1] = mul2(o2[i][1], corr2);
            float4 pw; pw.x = p0; pw.y = p1; pw.z = p2; pw.w = p3;
            *(float4*)(Ps + (tm * 4 + i) * TSTR + tn * 4) = pw;
        }
        __syncthreads();

        // ---- PV: o[i][d] += sum_n Ps[row_i][n] * Vs[n][d]  (tn reinterpreted as d-cols) ----
        #pragma unroll 4
        for (int nn0 = 0; nn0 < BN; nn0 += 4) {
            float4 pa[4];
            #pragma unroll
            for (int i = 0; i < 4; i++)
                pa[i] = *(const float4*)(Ps + (tm * 4 + i) * TSTR + nn0);
            #pragma unroll
            for (int t = 0; t < 4; t++) {
                const ulonglong2 vv = *(const ulonglong2*)(Vs + (nn0 + t) * TSTR + tn * 4);
                #pragma unroll
                for (int i = 0; i < 4; i++) {
                    const float a = (t == 0) ? pa[i].x : (t == 1) ? pa[i].y
                                  : (t == 2) ? pa[i].z : pa[i].w;
                    const ull a2 = pk2(a, a);
                    o2[i][0] = fma2(a2, vv.x, o2[i][0]);
                    o2[i][1] = fma2(a2, vv.y, o2[i][1]);
                }
            }
        }
    }

    // ---- epilogue: normalize and store out[b][s][h*D + d] ----
    #pragma unroll
    for (int i = 0; i < 4; i++) {
        const float inv = 1.0f / lrow[i];
        float4 r;
        upk2(o2[i][0], r.x, r.y);
        upk2(o2[i][1], r.z, r.w);
        r.x *= inv; r.y *= inv; r.z *= inv; r.w *= inv;
        const int row = m0 + tm * 4 + i;
        *(float4*)(outg + ((size_t)b * SDIM + row) * (HEADS * HDIM) + h * HDIM + tn * 4) = r;
    }
}

extern "C" void kernel_launch(void* const* d_in, const int* in_sizes, int n_in,
                              void* d_out, int out_size) {
    const float*         q    = (const float*)d_in[0];
    const float*         k    = (const float*)d_in[1];
    const float*         v    = (const float*)d_in[2];
    const float*         bias = (const float*)d_in[3];
    const unsigned char* mask = (const unsigned char*)d_in[4];
    float* out = (float*)d_out;

    detect_mask_kernel<<<1, 1>>>((const unsigned int*)mask);

    const int smem_bytes = 4 * BM * TSTR * (int)sizeof(float);  // 69632 B
    cudaFuncSetAttribute(attn_kernel, cudaFuncAttributeMaxDynamicSharedMemorySize, smem_bytes);

    dim3 grid(SDIM / BM, HEADS, BATCH);
    attn_kernel<<<grid, 256, smem_bytes>>>(q, k, v, bias, mask, out);
}

// round 3
// speedup vs baseline: 1.2299x; 1.2299x over previous
#include <cuda_runtime.h>
#include <cuda_fp16.h>
#include <cstdint>

#define SDIM 2048
#define HEADS 16
#define HDIM 64
#define BM 64
#define BN 64
#define KSTR 72   // smem row stride in halfs: frag-load bank == laneid (conflict-free)

__device__ int g_mask_word_mode;

__global__ void detect_mask_kernel(const unsigned int* m) {
    int word_mode = 1;
    for (int i = 0; i < 1024; i++) {
        const unsigned int w = m[i];
        if (w != 0u && w != 1u && w != 0x3F800000u) { word_mode = 0; break; }
    }
    g_mask_word_mode = word_mode;
}

__device__ __forceinline__ uint32_t pack_h2(float x, float y) {
    __half2 h = __floats2half2_rn(x, y);
    return *reinterpret_cast<uint32_t*>(&h);
}
__device__ __forceinline__ void split_h2(float x, float y, uint32_t& hi, uint32_t& lo) {
    const __half hx = __float2half_rn(x), hy = __float2half_rn(y);
    __half2 hp = __halves2half2(hx, hy);
    hi = *reinterpret_cast<uint32_t*>(&hp);
    lo = pack_h2(x - __half2float(hx), y - __half2float(hy));
}
__device__ __forceinline__ void mma16816(float* c, const uint32_t* a, uint32_t b0, uint32_t b1) {
    asm volatile(
        "mma.sync.aligned.m16n8k16.row.col.f32.f16.f16.f32 "
        "{%0,%1,%2,%3}, {%4,%5,%6,%7}, {%8,%9}, {%0,%1,%2,%3};"
        : "+f"(c[0]), "+f"(c[1]), "+f"(c[2]), "+f"(c[3])
        : "r"(a[0]), "r"(a[1]), "r"(a[2]), "r"(a[3]), "r"(b0), "r"(b1));
}

__global__ __launch_bounds__(128, 2)
void attn_kernel(const float* __restrict__ qg, const float* __restrict__ kg,
                 const float* __restrict__ vg, const float* __restrict__ biasg,
                 const unsigned char* __restrict__ maskg, float* __restrict__ outg)
{
    __shared__ __half KsH[BN][KSTR];   // K tile [key][d], hi part
    __shared__ __half KsL[BN][KSTR];   // lo part
    __shared__ __half VtH[HDIM][KSTR]; // V tile transposed [d][key], hi
    __shared__ __half VtL[HDIM][KSTR]; // lo

    const int tid  = threadIdx.x;
    const int warp = tid >> 5, lane = tid & 31;
    const int q4   = lane & 3;          // quad index (col pair selector)
    const int r8   = lane >> 2;         // group index (row / n selector)
    const int m0   = blockIdx.x * BM, h = blockIdx.y, b = blockIdx.z;
    const int row0 = m0 + warp * 16 + r8, row1 = row0 + 8;
    const int wordm = g_mask_word_mode;

    // ---- Q fragments (x8 scale), fp16 hi/lo split, resident in registers ----
    uint32_t qh[4][4], ql[4][4];
    {
        const size_t qb0 = (((size_t)b * SDIM + row0) * HEADS + h) * HDIM;
        const size_t qb1 = (((size_t)b * SDIM + row1) * HEADS + h) * HDIM;
        #pragma unroll
        for (int dk = 0; dk < 4; dk++) {
            const int c0 = dk * 16 + 2 * q4;
            const float2 x00 = *(const float2*)(qg + qb0 + c0);
            const float2 x10 = *(const float2*)(qg + qb1 + c0);
            const float2 x01 = *(const float2*)(qg + qb0 + c0 + 8);
            const float2 x11 = *(const float2*)(qg + qb1 + c0 + 8);
            split_h2(8.f * x00.x, 8.f * x00.y, qh[dk][0], ql[dk][0]);
            split_h2(8.f * x10.x, 8.f * x10.y, qh[dk][1], ql[dk][1]);
            split_h2(8.f * x01.x, 8.f * x01.y, qh[dk][2], ql[dk][2]);
            split_h2(8.f * x11.x, 8.f * x11.y, qh[dk][3], ql[dk][3]);
        }
    }

    float o[8][4];
    #pragma unroll
    for (int i = 0; i < 8; i++) { o[i][0] = o[i][1] = o[i][2] = o[i][3] = 0.f; }
    float mro0 = -1e30f, mro1 = -1e30f, lro0 = 0.f, lro1 = 0.f;

    const size_t biasb0 = (((size_t)b * HEADS + h) * SDIM + row0) * SDIM;
    const size_t biasb1 = (((size_t)b * HEADS + h) * SDIM + row1) * SDIM;
    const size_t maskb0 = ((size_t)b * SDIM + row0) * SDIM;
    const size_t maskb1 = ((size_t)b * SDIM + row1) * SDIM;

    for (int n0 = 0; n0 < SDIM; n0 += BN) {
        __syncthreads();
        // ---- K tile: coalesced load, hi/lo split, natural [key][d] layout ----
        #pragma unroll
        for (int it = 0; it < 8; it++) {
            const int idx = it * 128 + tid;
            const int r = idx >> 4, d4 = (idx & 15) << 2;
            const float4 kx = *(const float4*)(kg + (((size_t)b * SDIM + n0 + r) * HEADS + h) * HDIM + d4);
            uint32_t h01, l01, h23, l23;
            split_h2(kx.x, kx.y, h01, l01);
            split_h2(kx.z, kx.w, h23, l23);
            *(uint32_t*)&KsH[r][d4]     = h01;
            *(uint32_t*)&KsH[r][d4 + 2] = h23;
            *(uint32_t*)&KsL[r][d4]     = l01;
            *(uint32_t*)&KsL[r][d4 + 2] = l23;
        }
        // ---- V tile: row-per-lane gmem load, transposed store [d][key] (merge-conflict-free) ----
        {
            const int vrow = tid & 63, dblk = (tid >> 6) * 4;
            #pragma unroll
            for (int it = 0; it < 8; it++) {
                const int d4 = it * 8 + dblk;
                const float4 vx = *(const float4*)(vg + (((size_t)b * SDIM + n0 + vrow) * HEADS + h) * HDIM + d4);
                const float e[4] = {vx.x, vx.y, vx.z, vx.w};
                #pragma unroll
                for (int j = 0; j < 4; j++) {
                    const __half hx = __float2half_rn(e[j]);
                    VtH[d4 + j][vrow] = hx;
                    VtL[d4 + j][vrow] = __float2half_rn(e[j] - __half2float(hx));
                }
            }
        }
        __syncthreads();

        // ---- QK^T via 3-pass fp16-split HMMA ----
        float c[8][4];
        #pragma unroll
        for (int i = 0; i < 8; i++) { c[i][0] = c[i][1] = c[i][2] = c[i][3] = 0.f; }
        #pragma unroll
        for (int dk = 0; dk < 4; dk++) {
            #pragma unroll
            for (int nt = 0; nt < 8; nt++) {
                const uint32_t bh0 = *(const uint32_t*)&KsH[nt * 8 + r8][dk * 16 + 2 * q4];
                const uint32_t bh1 = *(const uint32_t*)&KsH[nt * 8 + r8][dk * 16 + 2 * q4 + 8];
                const uint32_t bl0 = *(const uint32_t*)&KsL[nt * 8 + r8][dk * 16 + 2 * q4];
                const uint32_t bl1 = *(const uint32_t*)&KsL[nt * 8 + r8][dk * 16 + 2 * q4 + 8];
                mma16816(c[nt], qh[dk], bh0, bh1);
                mma16816(c[nt], qh[dk], bl0, bl1);
                mma16816(c[nt], ql[dk], bh0, bh1);
            }
        }

        // ---- bias + mask (masked score := exactly 0, stays in softmax) ----
        #pragma unroll
        for (int nt = 0; nt < 8; nt++) {
            const int col = n0 + nt * 8 + 2 * q4;
            const float2 bb0 = *(const float2*)(biasg + biasb0 + col);
            const float2 bb1 = *(const float2*)(biasg + biasb1 + col);
            int k00, k01, k10, k11;
            if (wordm) {
                const int2 w0 = *(const int2*)((const int*)maskg + maskb0 + col);
                const int2 w1 = *(const int2*)((const int*)maskg + maskb1 + col);
                k00 = (w0.x != 0); k01 = (w0.y != 0);
                k10 = (w1.x != 0); k11 = (w1.y != 0);
            } else {
                const unsigned short s0 = *(const unsigned short*)(maskg + maskb0 + col);
                const unsigned short s1 = *(const unsigned short*)(maskg + maskb1 + col);
                k00 = (s0 & 0xff) != 0; k01 = (s0 >> 8) != 0;
                k10 = (s1 & 0xff) != 0; k11 = (s1 >> 8) != 0;
            }
            c[nt][0] = k00 ? 0.f : c[nt][0] + bb0.x;
            c[nt][1] = k01 ? 0.f : c[nt][1] + bb0.y;
            c[nt][2] = k10 ? 0.f : c[nt][2] + bb1.x;
            c[nt][3] = k11 ? 0.f : c[nt][3] + bb1.y;
        }

        // ---- online softmax (quad-wide reduction; rows row0 and row1) ----
        float mx0 = -1e30f, mx1 = -1e30f;
        #pragma unroll
        for (int nt = 0; nt < 8; nt++) {
            mx0 = fmaxf(mx0, fmaxf(c[nt][0], c[nt][1]));
            mx1 = fmaxf(mx1, fmaxf(c[nt][2], c[nt][3]));
        }
        mx0 = fmaxf(mx0, __shfl_xor_sync(0xffffffffu, mx0, 1));
        mx0 = fmaxf(mx0, __shfl_xor_sync(0xffffffffu, mx0, 2));
        mx1 = fmaxf(mx1, __shfl_xor_sync(0xffffffffu, mx1, 1));
        mx1 = fmaxf(mx1, __shfl_xor_sync(0xffffffffu, mx1, 2));
        const float mn0 = fmaxf(mro0, mx0), mn1 = fmaxf(mro1, mx1);
        const float corr0 = __expf(mro0 - mn0), corr1 = __expf(mro1 - mn1);
        mro0 = mn0; mro1 = mn1;
        float sum0 = 0.f, sum1 = 0.f;
        #pragma unroll
        for (int nt = 0; nt < 8; nt++) {
            c[nt][0] = __expf(c[nt][0] - mn0);
            c[nt][1] = __expf(c[nt][1] - mn0);
            c[nt][2] = __expf(c[nt][2] - mn1);
            c[nt][3] = __expf(c[nt][3] - mn1);
            sum0 += c[nt][0] + c[nt][1];
            sum1 += c[nt][2] + c[nt][3];
        }
        sum0 += __shfl_xor_sync(0xffffffffu, sum0, 1);
        sum0 += __shfl_xor_sync(0xffffffffu, sum0, 2);
        sum1 += __shfl_xor_sync(0xffffffffu, sum1, 1);
        sum1 += __shfl_xor_sync(0xffffffffu, sum1, 2);
        lro0 = lro0 * corr0 + sum0;
        lro1 = lro1 * corr1 + sum1;
        #pragma unroll
        for (int dn = 0; dn < 8; dn++) {
            o[dn][0] *= corr0; o[dn][1] *= corr0;
            o[dn][2] *= corr1; o[dn][3] *= corr1;
        }

        // ---- P fragments: C-layout -> A-layout in registers, fp16 hi/lo split ----
        uint32_t ph[4][4], pl[4][4];
        #pragma unroll
        for (int kt = 0; kt < 4; kt++) {
            split_h2(c[2 * kt][0],     c[2 * kt][1],     ph[kt][0], pl[kt][0]);
            split_h2(c[2 * kt][2],     c[2 * kt][3],     ph[kt][1], pl[kt][1]);
            split_h2(c[2 * kt + 1][0], c[2 * kt + 1][1], ph[kt][2], pl[kt][2]);
            split_h2(c[2 * kt + 1][2], c[2 * kt + 1][3], ph[kt][3], pl[kt][3]);
        }

        // ---- P·V via 3-pass fp16-split HMMA ----
        #pragma unroll
        for (int kt = 0; kt < 4; kt++) {
            #pragma unroll
            for (int dn = 0; dn < 8; dn++) {
                const uint32_t bh0 = *(const uint32_t*)&VtH[dn * 8 + r8][kt * 16 + 2 * q4];
                const uint32_t bh1 = *(const uint32_t*)&VtH[dn * 8 + r8][kt * 16 + 2 * q4 + 8];
                const uint32_t bl0 = *(const uint32_t*)&VtL[dn * 8 + r8][kt * 16 + 2 * q4];
                const uint32_t bl1 = *(const uint32_t*)&VtL[dn * 8 + r8][kt * 16 + 2 * q4 + 8];
                mma16816(o[dn], ph[kt], bh0, bh1);
                mma16816(o[dn], ph[kt], bl0, bl1);
                mma16816(o[dn], pl[kt], bh0, bh1);
            }
        }
    }

    // ---- epilogue ----
    const float inv0 = 1.f / lro0, inv1 = 1.f / lro1;
    const size_t ob0 = ((size_t)b * SDIM + row0) * (HEADS * HDIM) + h * HDIM;
    const size_t ob1 = ((size_t)b * SDIM + row1) * (HEADS * HDIM) + h * HDIM;
    #pragma unroll
    for (int dn = 0; dn < 8; dn++) {
        float2 r0, r1;
        r0.x = o[dn][0] * inv0; r0.y = o[dn][1] * inv0;
        r1.x = o[dn][2] * inv1; r1.y = o[dn][3] * inv1;
        *(float2*)(outg + ob0 + dn * 8 + 2 * q4) = r0;
        *(float2*)(outg + ob1 + dn * 8 + 2 * q4) = r1;
    }
}

extern "C" void kernel_launch(void* const* d_in, const int* in_sizes, int n_in,
                              void* d_out, int out_size) {
    const float*         q    = (const float*)d_in[0];
    const float*         k    = (const float*)d_in[1];
    const float*         v    = (const float*)d_in[2];
    const float*         bias = (const float*)d_in[3];
    const unsigned char* mask = (const unsigned char*)d_in[4];
    float* out = (float*)d_out;

    detect_mask_kernel<<<1, 1>>>((const unsigned int*)mask);

    dim3 grid(SDIM / BM, HEADS, 2);
    attn_kernel<<<grid, 128>>>(q, k, v, bias, mask, out);
}

// round 9
// speedup vs baseline: 1.3445x; 1.0932x over previous
#include <cuda_runtime.h>
#include <cuda_fp16.h>
#include <cstdint>

#define SDIM 2048
#define HEADS 16
#define HDIM 64
#define BM 128
#define BN 64
#define NTILE (SDIM / BN)
#define RSTR 72        // halfs per padded row
#define ROWB 144       // bytes per padded row
#define PLANE 9216     // 64 rows * 144 B : one plane of one tile
#define BUFB 36864     // 4 planes (KH,KL,VH,VL)

__device__ __half g_KH[(size_t)2 * HEADS * SDIM * RSTR];
__device__ __half g_KL[(size_t)2 * HEADS * SDIM * RSTR];
__device__ __half g_VH[(size_t)2 * HEADS * SDIM * RSTR];
__device__ __half g_VL[(size_t)2 * HEADS * SDIM * RSTR];
__device__ int g_mask_word_mode;

__global__ void detect_mask_kernel(const unsigned int* m) {
    int word_mode = 1;
    for (int i = 0; i < 1024; i++) {
        const unsigned int w = m[i];
        if (w != 0u && w != 1u && w != 0x3F800000u) { word_mode = 0; break; }
    }
    g_mask_word_mode = word_mode;
}

__device__ __forceinline__ uint32_t pack_h2(float x, float y) {
    __half2 h = __floats2half2_rn(x, y);
    return *reinterpret_cast<uint32_t*>(&h);
}
__device__ __forceinline__ void split_h2(float x, float y, uint32_t& hi, uint32_t& lo) {
    const __half hx = __float2half_rn(x), hy = __float2half_rn(y);
    __half2 hp = __halves2half2(hx, hy);
    hi = *reinterpret_cast<uint32_t*>(&hp);
    lo = pack_h2(x - __half2float(hx), y - __half2float(hy));
}
__device__ __forceinline__ float ex2f(float x) {
    float r; asm("ex2.approx.f32 %0, %1;" : "=f"(r) : "f"(x)); return r;
}
__device__ __forceinline__ void mma16816(float* c, const uint32_t* a, uint32_t b0, uint32_t b1) {
    asm volatile(
        "mma.sync.aligned.m16n8k16.row.col.f32.f16.f16.f32 "
        "{%0,%1,%2,%3}, {%4,%5,%6,%7}, {%8,%9}, {%0,%1,%2,%3};"
        : "+f"(c[0]), "+f"(c[1]), "+f"(c[2]), "+f"(c[3])
        : "r"(a[0]), "r"(a[1]), "r"(a[2]), "r"(a[3]), "r"(b0), "r"(b1));
}
__device__ __forceinline__ void ldsm4(uint32_t& a, uint32_t& b, uint32_t& c, uint32_t& d, uint32_t addr) {
    asm volatile("ldmatrix.sync.aligned.m8n8.x4.shared.b16 {%0,%1,%2,%3}, [%4];"
                 : "=r"(a), "=r"(b), "=r"(c), "=r"(d) : "r"(addr));
}
__device__ __forceinline__ void ldsm4t(uint32_t& a, uint32_t& b, uint32_t& c, uint32_t& d, uint32_t addr) {
    asm volatile("ldmatrix.sync.aligned.m8n8.x4.trans.shared.b16 {%0,%1,%2,%3}, [%4];"
                 : "=r"(a), "=r"(b), "=r"(c), "=r"(d) : "r"(addr));
}
__device__ __forceinline__ void cpa16(uint32_t dst, const void* src) {
    asm volatile("cp.async.cg.shared.global [%0], [%1], 16;" :: "r"(dst), "l"(src));
}

// ---- one-shot K/V fp16 hi/lo prepack into padded [bh][s][72] planes ----
__global__ __launch_bounds__(256)
void prepack_kernel(const float* __restrict__ kg, const float* __restrict__ vg) {
    const int idx = blockIdx.x * 256 + threadIdx.x;   // B*S*H*16 quads
    const int d4q = idx & 15;
    const int h   = (idx >> 4) & 15;
    const int s   = (idx >> 8) & 2047;
    const int b   = idx >> 19;
    const size_t src = (((size_t)b * SDIM + s) * HEADS + h) * HDIM + d4q * 4;
    const size_t dst = ((size_t)(b * HEADS + h) * SDIM + s) * RSTR + d4q * 4;
    uint32_t h01, l01, h23, l23;
    const float4 kx = *(const float4*)(kg + src);
    split_h2(kx.x, kx.y, h01, l01); split_h2(kx.z, kx.w, h23, l23);
    *(uint32_t*)&g_KH[dst] = h01; *(uint32_t*)&g_KH[dst + 2] = h23;
    *(uint32_t*)&g_KL[dst] = l01; *(uint32_t*)&g_KL[dst + 2] = l23;
    const float4 vx = *(const float4*)(vg + src);
    split_h2(vx.x, vx.y, h01, l01); split_h2(vx.z, vx.w, h23, l23);
    *(uint32_t*)&g_VH[dst] = h01; *(uint32_t*)&g_VH[dst + 2] = h23;
    *(uint32_t*)&g_VL[dst] = l01; *(uint32_t*)&g_VL[dst + 2] = l23;
}

__global__ __launch_bounds__(256, 1)
void attn_kernel(const float* __restrict__ qg, const float* __restrict__ biasg,
                 const unsigned char* __restrict__ maskg, float* __restrict__ outg)
{
    extern __shared__ char smem[];
    const uint32_t sbase = (uint32_t)__cvta_generic_to_shared(smem);
    const int tid = threadIdx.x, warp = tid >> 5, lane = tid & 31;
    const int q4 = lane & 3, r8 = lane >> 2;
    const int m0 = blockIdx.x * BM, h = blockIdx.y, b = blockIdx.z;
    const int row0 = m0 + warp * 16 + r8, row1 = row0 + 8;
    const int wordm = g_mask_word_mode;
    const int bh = b * HEADS + h;

    // per-lane ldmatrix offsets (tl = which of the 4 x4-tiles this lane addresses)
    const int tl = lane >> 3, rr = lane & 7;
    const uint32_t koff = (uint32_t)((tl >> 1) * PLANE + (tl & 1) * 16 + rr * ROWB);
    const uint32_t voff = (uint32_t)(2 * PLANE + (tl >> 1) * PLANE + ((tl & 1) * 8 + rr) * ROWB);

    // cp.async chunk coords
    const int ccol = tid & 7, crb = tid >> 3;   // crb in 0..31

    // ---- Q fragments, scaled by 8*log2(e), fp16 hi/lo split ----
    const float QSC = 8.0f * 1.44269504088896341f;
    uint32_t qh[4][4], ql[4][4];
    {
        const size_t qb0 = (((size_t)b * SDIM + row0) * HEADS + h) * HDIM;
        const size_t qb1 = (((size_t)b * SDIM + row1) * HEADS + h) * HDIM;
        #pragma unroll
        for (int dk = 0; dk < 4; dk++) {
            const int c0 = dk * 16 + 2 * q4;
            const float2 x00 = *(const float2*)(qg + qb0 + c0);
            const float2 x10 = *(const float2*)(qg + qb1 + c0);
            const float2 x01 = *(const float2*)(qg + qb0 + c0 + 8);
            const float2 x11 = *(const float2*)(qg + qb1 + c0 + 8);
            split_h2(QSC * x00.x, QSC * x00.y, qh[dk][0], ql[dk][0]);
            split_h2(QSC * x10.x, QSC * x10.y, qh[dk][1], ql[dk][1]);
            split_h2(QSC * x01.x, QSC * x01.y, qh[dk][2], ql[dk][2]);
            split_h2(QSC * x11.x, QSC * x11.y, qh[dk][3], ql[dk][3]);
        }
    }

    float o[8][4];
    #pragma unroll
    for (int i = 0; i < 8; i++) { o[i][0] = o[i][1] = o[i][2] = o[i][3] = 0.f; }
    float mro0 = -1e30f, mro1 = -1e30f, lro0 = 0.f, lro1 = 0.f;

    const size_t biasb0 = (((size_t)b * HEADS + h) * SDIM + row0) * SDIM;
    const size_t biasb1 = (((size_t)b * HEADS + h) * SDIM + row1) * SDIM;
    const size_t maskb0 = ((size_t)b * SDIM + row0) * SDIM;
    const size_t maskb1 = ((size_t)b * SDIM + row1) * SDIM;

    // ---- async tile prefetch: 4 planes x 64 rows x 128B, 8 chunks/thread ----
    #define PREFETCH(T, BUFI) do {                                              \
        const uint32_t dstb_ = sbase + (BUFI) * BUFB;                           \
        const size_t rowbase_ = (size_t)bh * SDIM + (T) * BN;                   \
        _Pragma("unroll")                                                       \
        for (int i_ = 0; i_ < 8; i_++) {                                        \
            const int plane_ = i_ >> 1;                                         \
            const int r_ = (i_ & 1) * 32 + crb;                                 \
            const size_t so_ = (rowbase_ + r_) * RSTR + ccol * 8;               \
            const __half* sp_ = (plane_ == 0) ? (g_KH + so_)                    \
                              : (plane_ == 1) ? (g_KL + so_)                    \
                              : (plane_ == 2) ? (g_VH + so_) : (g_VL + so_);    \
            cpa16(dstb_ + plane_ * PLANE + r_ * ROWB + ccol * 16, sp_);         \
        }                                                                       \
        asm volatile("cp.async.commit_group;" ::: "memory");                    \
    } while (0)

    PREFETCH(0, 0);

    for (int t = 0; t < NTILE; t++) {
        const int bufi = t & 1;
        if (t + 1 < NTILE) {
            PREFETCH(t + 1, bufi ^ 1);
            asm volatile("cp.async.wait_group 1;" ::: "memory");
        } else {
            asm volatile("cp.async.wait_group 0;" ::: "memory");
        }
        __syncthreads();
        const uint32_t kb = sbase + bufi * BUFB;
        const int n0 = t * BN;

        // ---- QK^T : 3-pass fp16-split HMMA, B-frags via ldmatrix.x4 ----
        float c[8][4];
        #pragma unroll
        for (int i = 0; i < 8; i++) { c[i][0] = c[i][1] = c[i][2] = c[i][3] = 0.f; }
        #pragma unroll
        for (int dk = 0; dk < 4; dk++) {
            #pragma unroll
            for (int nt = 0; nt < 8; nt++) {
                uint32_t bh0, bh1, bl0, bl1;
                ldsm4(bh0, bh1, bl0, bl1, kb + koff + (uint32_t)(nt * 1152 + dk * 32));
                mma16816(c[nt], qh[dk], bh0, bh1);
                mma16816(c[nt], qh[dk], bl0, bl1);
                mma16816(c[nt], ql[dk], bh0, bh1);
            }
        }

        // ---- bias (x log2e) + mask (masked score := 0 in log2 domain too) ----
        const float L2E = 1.44269504088896341f;
        #pragma unroll
        for (int nt = 0; nt < 8; nt++) {
            const int col = n0 + nt * 8 + 2 * q4;
            const float2 bb0 = *(const float2*)(biasg + biasb0 + col);
            const float2 bb1 = *(const float2*)(biasg + biasb1 + col);
            int k00, k01, k10, k11;
            if (wordm) {
                const int2 w0 = *(const int2*)((const int*)maskg + maskb0 + col);
                const int2 w1 = *(const int2*)((const int*)maskg + maskb1 + col);
                k00 = (w0.x != 0); k01 = (w0.y != 0);
                k10 = (w1.x != 0); k11 = (w1.y != 0);
            } else {
                const unsigned short s0 = *(const unsigned short*)(maskg + maskb0 + col);
                const unsigned short s1 = *(const unsigned short*)(maskg + maskb1 + col);
                k00 = (s0 & 0xff) != 0; k01 = (s0 >> 8) != 0;
                k10 = (s1 & 0xff) != 0; k11 = (s1 >> 8) != 0;
            }
            c[nt][0] = k00 ? 0.f : fmaf(bb0.x, L2E, c[nt][0]);
            c[nt][1] = k01 ? 0.f : fmaf(bb0.y, L2E, c[nt][1]);
            c[nt][2] = k10 ? 0.f : fmaf(bb1.x, L2E, c[nt][2]);
            c[nt][3] = k11 ? 0.f : fmaf(bb1.y, L2E, c[nt][3]);
        }

        // ---- online softmax in log2 domain ----
        float mx0 = -1e30f, mx1 = -1e30f;
        #pragma unroll
        for (int nt = 0; nt < 8; nt++) {
            mx0 = fmaxf(mx0, fmaxf(c[nt][0], c[nt][1]));
            mx1 = fmaxf(mx1, fmaxf(c[nt][2], c[nt][3]));
        }
        mx0 = fmaxf(mx0, __shfl_xor_sync(0xffffffffu, mx0, 1));
        mx0 = fmaxf(mx0, __shfl_xor_sync(0xffffffffu, mx0, 2));
        mx1 = fmaxf(mx1, __shfl_xor_sync(0xffffffffu, mx1, 1));
        mx1 = fmaxf(mx1, __shfl_xor_sync(0xffffffffu, mx1, 2));
        const float mn0 = fmaxf(mro0, mx0), mn1 = fmaxf(mro1, mx1);
        const float corr0 = ex2f(mro0 - mn0), corr1 = ex2f(mro1 - mn1);
        mro0 = mn0; mro1 = mn1;
        float sum0 = 0.f, sum1 = 0.f;
        #pragma unroll
        for (int nt = 0; nt < 8; nt++) {
            c[nt][0] = ex2f(c[nt][0] - mn0);
            c[nt][1] = ex2f(c[nt][1] - mn0);
            c[nt][2] = ex2f(c[nt][2] - mn1);
            c[nt][3] = ex2f(c[nt][3] - mn1);
            sum0 += c[nt][0] + c[nt][1];
            sum1 += c[nt][2] + c[nt][3];
        }
        sum0 += __shfl_xor_sync(0xffffffffu, sum0, 1);
        sum0 += __shfl_xor_sync(0xffffffffu, sum0, 2);
        sum1 += __shfl_xor_sync(0xffffffffu, sum1, 1);
        sum1 += __shfl_xor_sync(0xffffffffu, sum1, 2);
        lro0 = lro0 * corr0 + sum0;
        lro1 = lro1 * corr1 + sum1;
        #pragma unroll
        for (int dn = 0; dn < 8; dn++) {
            o[dn][0] *= corr0; o[dn][1] *= corr0;
            o[dn][2] *= corr1; o[dn][3] *= corr1;
        }

        // ---- P fragments: C-layout -> A-layout in registers, fp16 hi/lo split ----
        uint32_t ph[4][4], pl[4][4];
        #pragma unroll
        for (int kt = 0; kt < 4; kt++) {
            split_h2(c[2 * kt][0],     c[2 * kt][1],     ph[kt][0], pl[kt][0]);
            split_h2(c[2 * kt][2],     c[2 * kt][3],     ph[kt][1], pl[kt][1]);
            split_h2(c[2 * kt + 1][0], c[2 * kt + 1][1], ph[kt][2], pl[kt][2]);
            split_h2(c[2 * kt + 1][2], c[2 * kt + 1][3], ph[kt][3], pl[kt][3]);
        }

        // ---- P.V : 3-pass, B-frags via ldmatrix.x4.trans on row-major V ----
        #pragma unroll
        for (int kt = 0; kt < 4; kt++) {
            #pragma unroll
            for (int dn = 0; dn < 8; dn++) {
                uint32_t vh0, vh1, vl0, vl1;
                ldsm4t(vh0, vh1, vl0, vl1, kb + voff + (uint32_t)(kt * 2304 + dn * 16));
                mma16816(o[dn], ph[kt], vh0, vh1);
                mma16816(o[dn], ph[kt], vl0, vl1);
                mma16816(o[dn], pl[kt], vh0, vh1);
            }
        }
        __syncthreads();
    }

    // ---- epilogue ----
    const float inv0 = 1.f / lro0, inv1 = 1.f / lro1;
    const size_t ob0 = ((size_t)b * SDIM + row0) * (HEADS * HDIM) + h * HDIM;
    const size_t ob1 = ((size_t)b * SDIM + row1) * (HEADS * HDIM) + h * HDIM;
    #pragma unroll
    for (int dn = 0; dn < 8; dn++) {
        float2 r0, r1;
        r0.x = o[dn][0] * inv0; r0.y = o[dn][1] * inv0;
        r1.x = o[dn][2] * inv1; r1.y = o[dn][3] * inv1;
        *(float2*)(outg + ob0 + dn * 8 + 2 * q4) = r0;
        *(float2*)(outg + ob1 + dn * 8 + 2 * q4) = r1;
    }
}

extern "C" void kernel_launch(void* const* d_in, const int* in_sizes, int n_in,
                              void* d_out, int out_size) {
    const float*         q    = (const float*)d_in[0];
    const float*         k    = (const float*)d_in[1];
    const float*         v    = (const float*)d_in[2];
    const float*         bias = (const float*)d_in[3];
    const unsigned char* mask = (const unsigned char*)d_in[4];
    float* out = (float*)d_out;

    detect_mask_kernel<<<1, 1>>>((const unsigned int*)mask);
    prepack_kernel<<<4096, 256>>>(k, v);

    cudaFuncSetAttribute(attn_kernel, cudaFuncAttributeMaxDynamicSharedMemorySize, 2 * BUFB);
    dim3 grid(SDIM / BM, HEADS, 2);
    attn_kernel<<<grid, 256, 2 * BUFB>>>(q, bias, mask, out);
}

// round 10
// speedup vs baseline: 2.2219x; 1.6526x over previous
#include <cuda_runtime.h>
#include <cuda_fp16.h>
#include <cstdint>

#define SDIM 2048
#define HEADS 16
#define HDIM 64
#define BM 128
#define BN 64
#define NTILE (SDIM / BN)
#define RSTR 72        // halfs per padded row
#define ROWB 144       // bytes per padded row
#define PLANE 9216     // 64 rows * 144 B : one plane of one tile
#define BUFB 36864     // 4 planes (KH,KL,VH,VL)
#define NSTAGE 3

__device__ __half g_KH[(size_t)2 * HEADS * SDIM * RSTR];
__device__ __half g_KL[(size_t)2 * HEADS * SDIM * RSTR];
__device__ __half g_VH[(size_t)2 * HEADS * SDIM * RSTR];
__device__ __half g_VL[(size_t)2 * HEADS * SDIM * RSTR];
__device__ int g_mask_word_mode;

__global__ void detect_mask_kernel(const unsigned int* m) {
    int bad = 0;
    #pragma unroll 8
    for (int i = threadIdx.x; i < 1024; i += 32) {
        const unsigned int w = m[i];
        bad |= (w != 0u && w != 1u && w != 0x3F800000u) ? 1 : 0;
    }
    const unsigned int any = __ballot_sync(0xffffffffu, bad);
    if (threadIdx.x == 0) g_mask_word_mode = (any == 0u) ? 1 : 0;
}

__device__ __forceinline__ uint32_t pack_h2(float x, float y) {
    __half2 h = __floats2half2_rn(x, y);
    return *reinterpret_cast<uint32_t*>(&h);
}
__device__ __forceinline__ void split_h2(float x, float y, uint32_t& hi, uint32_t& lo) {
    const __half hx = __float2half_rn(x), hy = __float2half_rn(y);
    __half2 hp = __halves2half2(hx, hy);
    hi = *reinterpret_cast<uint32_t*>(&hp);
    lo = pack_h2(x - __half2float(hx), y - __half2float(hy));
}
__device__ __forceinline__ float ex2f(float x) {
    float r; asm("ex2.approx.f32 %0, %1;" : "=f"(r) : "f"(x)); return r;
}
__device__ __forceinline__ void mma16816(float* c, const uint32_t* a, uint32_t b0, uint32_t b1) {
    asm volatile(
        "mma.sync.aligned.m16n8k16.row.col.f32.f16.f16.f32 "
        "{%0,%1,%2,%3}, {%4,%5,%6,%7}, {%8,%9}, {%0,%1,%2,%3};"
        : "+f"(c[0]), "+f"(c[1]), "+f"(c[2]), "+f"(c[3])
        : "r"(a[0]), "r"(a[1]), "r"(a[2]), "r"(a[3]), "r"(b0), "r"(b1));
}
__device__ __forceinline__ void ldsm4(uint32_t& a, uint32_t& b, uint32_t& c, uint32_t& d, uint32_t addr) {
    asm volatile("ldmatrix.sync.aligned.m8n8.x4.shared.b16 {%0,%1,%2,%3}, [%4];"
                 : "=r"(a), "=r"(b), "=r"(c), "=r"(d) : "r"(addr));
}
__device__ __forceinline__ void ldsm4t(uint32_t& a, uint32_t& b, uint32_t& c, uint32_t& d, uint32_t addr) {
    asm volatile("ldmatrix.sync.aligned.m8n8.x4.trans.shared.b16 {%0,%1,%2,%3}, [%4];"
                 : "=r"(a), "=r"(b), "=r"(c), "=r"(d) : "r"(addr));
}
__device__ __forceinline__ void cpa16(uint32_t dst, const void* src) {
    asm volatile("cp.async.cg.shared.global [%0], [%1], 16;" :: "r"(dst), "l"(src));
}

// ---- one-shot K/V fp16 hi/lo prepack into padded [bh][s][72] planes ----
__global__ __launch_bounds__(256)
void prepack_kernel(const float* __restrict__ kg, const float* __restrict__ vg) {
    const int idx = blockIdx.x * 256 + threadIdx.x;   // B*S*H*16 quads
    const int d4q = idx & 15;
    const int h   = (idx >> 4) & 15;
    const int s   = (idx >> 8) & 2047;
    const int b   = idx >> 19;
    const size_t src = (((size_t)b * SDIM + s) * HEADS + h) * HDIM + d4q * 4;
    const size_t dst = ((size_t)(b * HEADS + h) * SDIM + s) * RSTR + d4q * 4;
    uint32_t h01, l01, h23, l23;
    const float4 kx = *(const float4*)(kg + src);
    split_h2(kx.x, kx.y, h01, l01); split_h2(kx.z, kx.w, h23, l23);
    *(uint32_t*)&g_KH[dst] = h01; *(uint32_t*)&g_KH[dst + 2] = h23;
    *(uint32_t*)&g_KL[dst] = l01; *(uint32_t*)&g_KL[dst + 2] = l23;
    const float4 vx = *(const float4*)(vg + src);
    split_h2(vx.x, vx.y, h01, l01); split_h2(vx.z, vx.w, h23, l23);
    *(uint32_t*)&g_VH[dst] = h01; *(uint32_t*)&g_VH[dst + 2] = h23;
    *(uint32_t*)&g_VL[dst] = l01; *(uint32_t*)&g_VL[dst + 2] = l23;
}

__global__ __launch_bounds__(256, 1)
void attn_kernel(const float* __restrict__ qg, const float* __restrict__ biasg,
                 const unsigned char* __restrict__ maskg, float* __restrict__ outg)
{
    extern __shared__ char smem[];
    const uint32_t sbase = (uint32_t)__cvta_generic_to_shared(smem);
    const int tid = threadIdx.x, warp = tid >> 5, lane = tid & 31;
    const int q4 = lane & 3, r8 = lane >> 2;
    const int m0 = blockIdx.x * BM, h = blockIdx.y, b = blockIdx.z;
    const int row0 = m0 + warp * 16 + r8, row1 = row0 + 8;
    const int wordm = g_mask_word_mode;
    const int bh = b * HEADS + h;

    // per-lane ldmatrix offsets (tl = which of the 4 x4-tiles this lane addresses)
    const int tl = lane >> 3, rr = lane & 7;
    const uint32_t koff = (uint32_t)((tl >> 1) * PLANE + (tl & 1) * 16 + rr * ROWB);
    const uint32_t voff = (uint32_t)(2 * PLANE + (tl >> 1) * PLANE + ((tl & 1) * 8 + rr) * ROWB);

    // cp.async chunk coords
    const int ccol = tid & 7, crb = tid >> 3;   // crb in 0..31

    // ---- Q fragments, scaled by 8*log2(e), fp16 hi/lo split ----
    const float QSC = 8.0f * 1.44269504088896341f;
    uint32_t qh[4][4], ql[4][4];
    {
        const size_t qb0 = (((size_t)b * SDIM + row0) * HEADS + h) * HDIM;
        const size_t qb1 = (((size_t)b * SDIM + row1) * HEADS + h) * HDIM;
        #pragma unroll
        for (int dk = 0; dk < 4; dk++) {
            const int c0 = dk * 16 + 2 * q4;
            const float2 x00 = *(const float2*)(qg + qb0 + c0);
            const float2 x10 = *(const float2*)(qg + qb1 + c0);
            const float2 x01 = *(const float2*)(qg + qb0 + c0 + 8);
            const float2 x11 = *(const float2*)(qg + qb1 + c0 + 8);
            split_h2(QSC * x00.x, QSC * x00.y, qh[dk][0], ql[dk][0]);
            split_h2(QSC * x10.x, QSC * x10.y, qh[dk][1], ql[dk][1]);
            split_h2(QSC * x01.x, QSC * x01.y, qh[dk][2], ql[dk][2]);
            split_h2(QSC * x11.x, QSC * x11.y, qh[dk][3], ql[dk][3]);
        }
    }

    float o[8][4];
    #pragma unroll
    for (int i = 0; i < 8; i++) { o[i][0] = o[i][1] = o[i][2] = o[i][3] = 0.f; }
    float mro0 = -1e30f, mro1 = -1e30f, lro0 = 0.f, lro1 = 0.f;

    const size_t biasb0 = (((size_t)b * HEADS + h) * SDIM + row0) * SDIM;
    const size_t biasb1 = (((size_t)b * HEADS + h) * SDIM + row1) * SDIM;
    const size_t maskb0 = ((size_t)b * SDIM + row0) * SDIM;
    const size_t maskb1 = ((size_t)b * SDIM + row1) * SDIM;

    // ---- async tile prefetch: 4 planes x 64 rows x 128B, 8 chunks/thread ----
    #define PREFETCH(T, BUFI) do {                                              \
        const uint32_t dstb_ = sbase + (uint32_t)(BUFI) * BUFB;                 \
        const size_t rowbase_ = (size_t)bh * SDIM + (T) * BN;                   \
        _Pragma("unroll")                                                       \
        for (int i_ = 0; i_ < 8; i_++) {                                        \
            const int plane_ = i_ >> 1;                                         \
            const int r_ = (i_ & 1) * 32 + crb;                                 \
            const size_t so_ = (rowbase_ + r_) * RSTR + ccol * 8;               \
            const __half* sp_ = (plane_ == 0) ? (g_KH + so_)                    \
                              : (plane_ == 1) ? (g_KL + so_)                    \
                              : (plane_ == 2) ? (g_VH + so_) : (g_VL + so_);    \
            cpa16(dstb_ + plane_ * PLANE + r_ * ROWB + ccol * 16, sp_);         \
        }                                                                       \
        asm volatile("cp.async.commit_group;" ::: "memory");                    \
    } while (0)

    PREFETCH(0, 0);
    PREFETCH(1, 1);

    for (int t = 0; t < NTILE; t++) {
        if (t + 1 < NTILE) {
            asm volatile("cp.async.wait_group 1;" ::: "memory");
        } else {
            asm volatile("cp.async.wait_group 0;" ::: "memory");
        }
        __syncthreads();   // single barrier per tile: data ready + all warps done with t-1
        if (t + 2 < NTILE) PREFETCH(t + 2, (t + 2) % NSTAGE);

        const uint32_t kb = sbase + (uint32_t)(t % NSTAGE) * BUFB;
        const int n0 = t * BN;

        // ---- issue this tile's bias+mask loads FIRST (latency hidden under QK MMAs) ----
        float2 bb0a[8], bb1a[8];
        int2   m0a[8], m1a[8];
        #pragma unroll
        for (int nt = 0; nt < 8; nt++) {
            const int col = n0 + nt * 8 + 2 * q4;
            bb0a[nt] = *(const float2*)(biasg + biasb0 + col);
            bb1a[nt] = *(const float2*)(biasg + biasb1 + col);
            if (wordm) {
                m0a[nt] = *(const int2*)((const int*)maskg + maskb0 + col);
                m1a[nt] = *(const int2*)((const int*)maskg + maskb1 + col);
            } else {
                m0a[nt].x = *(const unsigned short*)(maskg + maskb0 + col);
                m1a[nt].x = *(const unsigned short*)(maskg + maskb1 + col);
                m0a[nt].y = 0; m1a[nt].y = 0;
            }
        }

        // ---- QK^T : 3-pass fp16-split HMMA, B-frags via ldmatrix.x4 ----
        float c[8][4];
        #pragma unroll
        for (int i = 0; i < 8; i++) { c[i][0] = c[i][1] = c[i][2] = c[i][3] = 0.f; }
        #pragma unroll
        for (int dk = 0; dk < 4; dk++) {
            #pragma unroll
            for (int nt = 0; nt < 8; nt++) {
                uint32_t bh0, bh1, bl0, bl1;
                ldsm4(bh0, bh1, bl0, bl1, kb + koff + (uint32_t)(nt * 1152 + dk * 32));
                mma16816(c[nt], qh[dk], bh0, bh1);
                mma16816(c[nt], qh[dk], bl0, bl1);
                mma16816(c[nt], ql[dk], bh0, bh1);
            }
        }

        // ---- bias (x log2e) + mask (masked score := 0 in log2 domain too) ----
        const float L2E = 1.44269504088896341f;
        #pragma unroll
        for (int nt = 0; nt < 8; nt++) {
            int k00, k01, k10, k11;
            if (wordm) {
                k00 = (m0a[nt].x != 0); k01 = (m0a[nt].y != 0);
                k10 = (m1a[nt].x != 0); k11 = (m1a[nt].y != 0);
            } else {
                k00 = (m0a[nt].x & 0xff) != 0; k01 = ((m0a[nt].x >> 8) & 0xff) != 0;
                k10 = (m1a[nt].x & 0xff) != 0; k11 = ((m1a[nt].x >> 8) & 0xff) != 0;
            }
            c[nt][0] = k00 ? 0.f : fmaf(bb0a[nt].x, L2E, c[nt][0]);
            c[nt][1] = k01 ? 0.f : fmaf(bb0a[nt].y, L2E, c[nt][1]);
            c[nt][2] = k10 ? 0.f : fmaf(bb1a[nt].x, L2E, c[nt][2]);
            c[nt][3] = k11 ? 0.f : fmaf(bb1a[nt].y, L2E, c[nt][3]);
        }

        // ---- online softmax in log2 domain ----
        float mx0 = -1e30f, mx1 = -1e30f;
        #pragma unroll
        for (int nt = 0; nt < 8; nt++) {
            mx0 = fmaxf(mx0, fmaxf(c[nt][0], c[nt][1]));
            mx1 = fmaxf(mx1, fmaxf(c[nt][2], c[nt][3]));
        }
        mx0 = fmaxf(mx0, __shfl_xor_sync(0xffffffffu, mx0, 1));
        mx0 = fmaxf(mx0, __shfl_xor_sync(0xffffffffu, mx0, 2));
        mx1 = fmaxf(mx1, __shfl_xor_sync(0xffffffffu, mx1, 1));
        mx1 = fmaxf(mx1, __shfl_xor_sync(0xffffffffu, mx1, 2));
        const float mn0 = fmaxf(mro0, mx0), mn1 = fmaxf(mro1, mx1);
        const float corr0 = ex2f(mro0 - mn0), corr1 = ex2f(mro1 - mn1);
        mro0 = mn0; mro1 = mn1;
        float sum0 = 0.f, sum1 = 0.f;
        #pragma unroll
        for (int nt = 0; nt < 8; nt++) {
            c[nt][0] = ex2f(c[nt][0] - mn0);
            c[nt][1] = ex2f(c[nt][1] - mn0);
            c[nt][2] = ex2f(c[nt][2] - mn1);
            c[nt][3] = ex2f(c[nt][3] - mn1);
            sum0 += c[nt][0] + c[nt][1];
            sum1 += c[nt][2] + c[nt][3];
        }
        sum0 += __shfl_xor_sync(0xffffffffu, sum0, 1);
        sum0 += __shfl_xor_sync(0xffffffffu, sum0, 2);
        sum1 += __shfl_xor_sync(0xffffffffu, sum1, 1);
        sum1 += __shfl_xor_sync(0xffffffffu, sum1, 2);
        lro0 = lro0 * corr0 + sum0;
        lro1 = lro1 * corr1 + sum1;
        #pragma unroll
        for (int dn = 0; dn < 8; dn++) {
            o[dn][0] *= corr0; o[dn][1] *= corr0;
            o[dn][2] *= corr1; o[dn][3] *= corr1;
        }

        // ---- P fragments: C-layout -> A-layout in registers, fp16 hi/lo split ----
        uint32_t ph[4][4], pl[4][4];
        #pragma unroll
        for (int kt = 0; kt < 4; kt++) {
            split_h2(c[2 * kt][0],     c[2 * kt][1],     ph[kt][0], pl[kt][0]);
            split_h2(c[2 * kt][2],     c[2 * kt][3],     ph[kt][1], pl[kt][1]);
            split_h2(c[2 * kt + 1][0], c[2 * kt + 1][1], ph[kt][2], pl[kt][2]);
            split_h2(c[2 * kt + 1][2], c[2 * kt + 1][3], ph[kt][3], pl[kt][3]);
        }

        // ---- P.V : 3-pass, B-frags via ldmatrix.x4.trans on row-major V ----
        #pragma unroll
        for (int kt = 0; kt < 4; kt++) {
            #pragma unroll
            for (int dn = 0; dn < 8; dn++) {
                uint32_t vh0, vh1, vl0, vl1;
                ldsm4t(vh0, vh1, vl0, vl1, kb + voff + (uint32_t)(kt * 2304 + dn * 16));
                mma16816(o[dn], ph[kt], vh0, vh1);
                mma16816(o[dn], ph[kt], vl0, vl1);
                mma16816(o[dn], pl[kt], vh0, vh1);
            }
        }
    }

    // ---- epilogue ----
    const float inv0 = 1.f / lro0, inv1 = 1.f / lro1;
    const size_t ob0 = ((size_t)b * SDIM + row0) * (HEADS * HDIM) + h * HDIM;
    const size_t ob1 = ((size_t)b * SDIM + row1) * (HEADS * HDIM) + h * HDIM;
    #pragma unroll
    for (int dn = 0; dn < 8; dn++) {
        float2 r0, r1;
        r0.x = o[dn][0] * inv0; r0.y = o[dn][1] * inv0;
        r1.x = o[dn][2] * inv1; r1.y = o[dn][3] * inv1;
        *(float2*)(outg + ob0 + dn * 8 + 2 * q4) = r0;
        *(float2*)(outg + ob1 + dn * 8 + 2 * q4) = r1;
    }
}

extern "C" void kernel_launch(void* const* d_in, const int* in_sizes, int n_in,
                              void* d_out, int out_size) {
    const float*         q    = (const float*)d_in[0];
    const float*         k    = (const float*)d_in[1];
    const float*         v    = (const float*)d_in[2];
    const float*         bias = (const float*)d_in[3];
    const unsigned char* mask = (const unsigned char*)d_in[4];
    float* out = (float*)d_out;

    detect_mask_kernel<<<1, 32>>>((const unsigned int*)mask);
    prepack_kernel<<<4096, 256>>>(k, v);

    cudaFuncSetAttribute(attn_kernel, cudaFuncAttributeMaxDynamicSharedMemorySize, NSTAGE * BUFB);
    dim3 grid(SDIM / BM, HEADS, 2);
    attn_kernel<<<grid, 256, NSTAGE * BUFB>>>(q, bias, mask, out);
}

// round 11
// speedup vs baseline: 2.4338x; 1.0954x over previous
#include <cuda_runtime.h>
#include <cuda_fp16.h>
#include <cstdint>

#define SDIM 2048
#define HEADS 16
#define HDIM 64
#define BM 128
#define BN 64
#define NTILE (SDIM / BN)
#define RSTR 72        // halfs per padded row
#define ROWB 144       // bytes per padded row
#define PLANE 9216     // 64 rows * 144 B : one plane of one tile
#define BUFB 36864     // 4 planes (KH,KL,VH,VL)
#define NSTAGE 3
#define ONES2 0x3C003C00u   // half2(1.0, 1.0)

__device__ __half g_KH[(size_t)2 * HEADS * SDIM * RSTR];
__device__ __half g_KL[(size_t)2 * HEADS * SDIM * RSTR];
__device__ __half g_VH[(size_t)2 * HEADS * SDIM * RSTR];
__device__ __half g_VL[(size_t)2 * HEADS * SDIM * RSTR];
__device__ int g_mask_word_mode;

__global__ void detect_mask_kernel(const unsigned int* m) {
    int bad = 0;
    #pragma unroll 8
    for (int i = threadIdx.x; i < 1024; i += 32) {
        const unsigned int w = m[i];
        bad |= (w != 0u && w != 1u && w != 0x3F800000u) ? 1 : 0;
    }
    const unsigned int any = __ballot_sync(0xffffffffu, bad);
    if (threadIdx.x == 0) g_mask_word_mode = (any == 0u) ? 1 : 0;
}

__device__ __forceinline__ uint32_t pack_h2(float x, float y) {
    __half2 h = __floats2half2_rn(x, y);
    return *reinterpret_cast<uint32_t*>(&h);
}
__device__ __forceinline__ void split_h2(float x, float y, uint32_t& hi, uint32_t& lo) {
    const __half hx = __float2half_rn(x), hy = __float2half_rn(y);
    __half2 hp = __halves2half2(hx, hy);
    hi = *reinterpret_cast<uint32_t*>(&hp);
    lo = pack_h2(x - __half2float(hx), y - __half2float(hy));
}
// pack two fp32 into half2 in ONE cvt (lo -> low half, hi -> high half)
__device__ __forceinline__ uint32_t cvt_h2(float lo, float hi) {
    uint32_t d; asm("cvt.rn.f16x2.f32 %0, %1, %2;" : "=r"(d) : "f"(hi), "f"(lo)); return d;
}
__device__ __forceinline__ float ex2f(float x) {
    float r; asm("ex2.approx.f32 %0, %1;" : "=f"(r) : "f"(x)); return r;
}
__device__ __forceinline__ void mma16816(float* c, const uint32_t* a, uint32_t b0, uint32_t b1) {
    asm volatile(
        "mma.sync.aligned.m16n8k16.row.col.f32.f16.f16.f32 "
        "{%0,%1,%2,%3}, {%4,%5,%6,%7}, {%8,%9}, {%0,%1,%2,%3};"
        : "+f"(c[0]), "+f"(c[1]), "+f"(c[2]), "+f"(c[3])
        : "r"(a[0]), "r"(a[1]), "r"(a[2]), "r"(a[3]), "r"(b0), "r"(b1));
}
__device__ __forceinline__ void ldsm4(uint32_t& a, uint32_t& b, uint32_t& c, uint32_t& d, uint32_t addr) {
    asm volatile("ldmatrix.sync.aligned.m8n8.x4.shared.b16 {%0,%1,%2,%3}, [%4];"
                 : "=r"(a), "=r"(b), "=r"(c), "=r"(d) : "r"(addr));
}
__device__ __forceinline__ void ldsm4t(uint32_t& a, uint32_t& b, uint32_t& c, uint32_t& d, uint32_t addr) {
    asm volatile("ldmatrix.sync.aligned.m8n8.x4.trans.shared.b16 {%0,%1,%2,%3}, [%4];"
                 : "=r"(a), "=r"(b), "=r"(c), "=r"(d) : "r"(addr));
}
__device__ __forceinline__ void cpa16(uint32_t dst, const void* src) {
    asm volatile("cp.async.cg.shared.global [%0], [%1], 16;" :: "r"(dst), "l"(src));
}

// ---- one-shot K/V fp16 hi/lo prepack into padded [bh][s][72] planes ----
__global__ __launch_bounds__(256)
void prepack_kernel(const float* __restrict__ kg, const float* __restrict__ vg) {
    const int idx = blockIdx.x * 256 + threadIdx.x;   // B*S*H*16 quads
    const int d4q = idx & 15;
    const int h   = (idx >> 4) & 15;
    const int s   = (idx >> 8) & 2047;
    const int b   = idx >> 19;
    const size_t src = (((size_t)b * SDIM + s) * HEADS + h) * HDIM + d4q * 4;
    const size_t dst = ((size_t)(b * HEADS + h) * SDIM + s) * RSTR + d4q * 4;
    uint32_t h01, l01, h23, l23;
    const float4 kx = *(const float4*)(kg + src);
    split_h2(kx.x, kx.y, h01, l01); split_h2(kx.z, kx.w, h23, l23);
    *(uint32_t*)&g_KH[dst] = h01; *(uint32_t*)&g_KH[dst + 2] = h23;
    *(uint32_t*)&g_KL[dst] = l01; *(uint32_t*)&g_KL[dst + 2] = l23;
    const float4 vx = *(const float4*)(vg + src);
    split_h2(vx.x, vx.y, h01, l01); split_h2(vx.z, vx.w, h23, l23);
    *(uint32_t*)&g_VH[dst] = h01; *(uint32_t*)&g_VH[dst + 2] = h23;
    *(uint32_t*)&g_VL[dst] = l01; *(uint32_t*)&g_VL[dst + 2] = l23;
}

__global__ __launch_bounds__(256, 1)
void attn_kernel(const float* __restrict__ qg, const float* __restrict__ biasg,
                 const unsigned char* __restrict__ maskg, float* __restrict__ outg)
{
    extern __shared__ char smem[];
    const uint32_t sbase = (uint32_t)__cvta_generic_to_shared(smem);
    const int tid = threadIdx.x, warp = tid >> 5, lane = tid & 31;
    const int q4 = lane & 3, r8 = lane >> 2;
    const int m0 = blockIdx.x * BM, h = blockIdx.y, b = blockIdx.z;
    const int row0 = m0 + warp * 16 + r8, row1 = row0 + 8;
    const int wordm = g_mask_word_mode;
    const int bh = b * HEADS + h;

    // per-lane ldmatrix offsets (tl = which of the 4 x4-tiles this lane addresses)
    const int tl = lane >> 3, rr = lane & 7;
    const uint32_t koff = (uint32_t)((tl >> 1) * PLANE + (tl & 1) * 16 + rr * ROWB);
    const uint32_t voff = (uint32_t)(2 * PLANE + (tl >> 1) * PLANE + ((tl & 1) * 8 + rr) * ROWB);

    // cp.async chunk coords
    const int ccol = tid & 7, crb = tid >> 3;   // crb in 0..31

    // ---- Q fragments, scaled by 8*log2(e), fp16 hi/lo split ----
    const float QSC = 8.0f * 1.44269504088896341f;
    uint32_t qh[4][4], ql[4][4];
    {
        const size_t qb0 = (((size_t)b * SDIM + row0) * HEADS + h) * HDIM;
        const size_t qb1 = (((size_t)b * SDIM + row1) * HEADS + h) * HDIM;
        #pragma unroll
        for (int dk = 0; dk < 4; dk++) {
            const int c0 = dk * 16 + 2 * q4;
            const float2 x00 = *(const float2*)(qg + qb0 + c0);
            const float2 x10 = *(const float2*)(qg + qb1 + c0);
            const float2 x01 = *(const float2*)(qg + qb0 + c0 + 8);
            const float2 x11 = *(const float2*)(qg + qb1 + c0 + 8);
            split_h2(QSC * x00.x, QSC * x00.y, qh[dk][0], ql[dk][0]);
            split_h2(QSC * x10.x, QSC * x10.y, qh[dk][1], ql[dk][1]);
            split_h2(QSC * x01.x, QSC * x01.y, qh[dk][2], ql[dk][2]);
            split_h2(QSC * x11.x, QSC * x11.y, qh[dk][3], ql[dk][3]);
        }
    }

    float o[8][4];
    #pragma unroll
    for (int i = 0; i < 8; i++) { o[i][0] = o[i][1] = o[i][2] = o[i][3] = 0.f; }
    float mro0 = -1e30f, mro1 = -1e30f, lro0 = 0.f, lro1 = 0.f;

    const size_t biasb0 = (((size_t)b * HEADS + h) * SDIM + row0) * SDIM;
    const size_t biasb1 = (((size_t)b * HEADS + h) * SDIM + row1) * SDIM;
    const size_t maskb0 = ((size_t)b * SDIM + row0) * SDIM;
    const size_t maskb1 = ((size_t)b * SDIM + row1) * SDIM;

    // ---- async tile prefetch: 4 planes x 64 rows x 128B, 8 chunks/thread ----
    #define PREFETCH(T, BUFI) do {                                              \
        const uint32_t dstb_ = sbase + (uint32_t)(BUFI) * BUFB;                 \
        const size_t rowbase_ = (size_t)bh * SDIM + (T) * BN;                   \
        _Pragma("unroll")                                                       \
        for (int i_ = 0; i_ < 8; i_++) {                                        \
            const int plane_ = i_ >> 1;                                         \
            const int r_ = (i_ & 1) * 32 + crb;                                 \
            const size_t so_ = (rowbase_ + r_) * RSTR + ccol * 8;               \
            const __half* sp_ = (plane_ == 0) ? (g_KH + so_)                    \
                              : (plane_ == 1) ? (g_KL + so_)                    \
                              : (plane_ == 2) ? (g_VH + so_) : (g_VL + so_);    \
            cpa16(dstb_ + plane_ * PLANE + r_ * ROWB + ccol * 16, sp_);         \
        }                                                                       \
        asm volatile("cp.async.commit_group;" ::: "memory");                    \
    } while (0)

    PREFETCH(0, 0);
    PREFETCH(1, 1);

    for (int t = 0; t < NTILE; t++) {
        if (t + 1 < NTILE) {
            asm volatile("cp.async.wait_group 1;" ::: "memory");
        } else {
            asm volatile("cp.async.wait_group 0;" ::: "memory");
        }
        __syncthreads();   // single barrier per tile: data ready + all warps done with t-1
        if (t + 2 < NTILE) PREFETCH(t + 2, (t + 2) % NSTAGE);

        const uint32_t kb = sbase + (uint32_t)(t % NSTAGE) * BUFB;
        const int n0 = t * BN;

        // ---- issue this tile's bias+mask loads FIRST (latency hidden under QK MMAs) ----
        float2 bb0a[8], bb1a[8];
        int2   m0a[8], m1a[8];
        #pragma unroll
        for (int nt = 0; nt < 8; nt++) {
            const int col = n0 + nt * 8 + 2 * q4;
            bb0a[nt] = *(const float2*)(biasg + biasb0 + col);
            bb1a[nt] = *(const float2*)(biasg + biasb1 + col);
            if (wordm) {
                m0a[nt] = *(const int2*)((const int*)maskg + maskb0 + col);
                m1a[nt] = *(const int2*)((const int*)maskg + maskb1 + col);
            } else {
                m0a[nt].x = *(const unsigned short*)(maskg + maskb0 + col);
                m1a[nt].x = *(const unsigned short*)(maskg + maskb1 + col);
                m0a[nt].y = 0; m1a[nt].y = 0;
            }
        }

        // ---- QK^T : 3-pass fp16-split HMMA, B-frags via ldmatrix.x4 ----
        float c[8][4];
        #pragma unroll
        for (int i = 0; i < 8; i++) { c[i][0] = c[i][1] = c[i][2] = c[i][3] = 0.f; }
        #pragma unroll
        for (int dk = 0; dk < 4; dk++) {
            #pragma unroll
            for (int nt = 0; nt < 8; nt++) {
                uint32_t bh0, bh1, bl0, bl1;
                ldsm4(bh0, bh1, bl0, bl1, kb + koff + (uint32_t)(nt * 1152 + dk * 32));
                mma16816(c[nt], qh[dk], bh0, bh1);
                mma16816(c[nt], qh[dk], bl0, bl1);
                mma16816(c[nt], ql[dk], bh0, bh1);
            }
        }

        // ---- bias (x log2e) + mask (masked score := 0 in log2 domain too) ----
        const float L2E = 1.44269504088896341f;
        #pragma unroll
        for (int nt = 0; nt < 8; nt++) {
            int k00, k01, k10, k11;
            if (wordm) {
                k00 = (m0a[nt].x != 0); k01 = (m0a[nt].y != 0);
                k10 = (m1a[nt].x != 0); k11 = (m1a[nt].y != 0);
            } else {
                k00 = (m0a[nt].x & 0xff) != 0; k01 = ((m0a[nt].x >> 8) & 0xff) != 0;
                k10 = (m1a[nt].x & 0xff) != 0; k11 = ((m1a[nt].x >> 8) & 0xff) != 0;
            }
            c[nt][0] = k00 ? 0.f : fmaf(bb0a[nt].x, L2E, c[nt][0]);
            c[nt][1] = k01 ? 0.f : fmaf(bb0a[nt].y, L2E, c[nt][1]);
            c[nt][2] = k10 ? 0.f : fmaf(bb1a[nt].x, L2E, c[nt][2]);
            c[nt][3] = k11 ? 0.f : fmaf(bb1a[nt].y, L2E, c[nt][3]);
        }

        // ---- online softmax in log2 domain (max via shfl; sum via ones-MMA below) ----
        float mx0 = -1e30f, mx1 = -1e30f;
        #pragma unroll
        for (int nt = 0; nt < 8; nt++) {
            mx0 = fmaxf(mx0, fmaxf(c[nt][0], c[nt][1]));
            mx1 = fmaxf(mx1, fmaxf(c[nt][2], c[nt][3]));
        }
        mx0 = fmaxf(mx0, __shfl_xor_sync(0xffffffffu, mx0, 1));
        mx0 = fmaxf(mx0, __shfl_xor_sync(0xffffffffu, mx0, 2));
        mx1 = fmaxf(mx1, __shfl_xor_sync(0xffffffffu, mx1, 1));
        mx1 = fmaxf(mx1, __shfl_xor_sync(0xffffffffu, mx1, 2));
        const float mn0 = fmaxf(mro0, mx0), mn1 = fmaxf(mro1, mx1);
        const float corr0 = ex2f(mro0 - mn0), corr1 = ex2f(mro1 - mn1);
        mro0 = mn0; mro1 = mn1;
        #pragma unroll
        for (int dn = 0; dn < 8; dn++) {
            o[dn][0] *= corr0; o[dn][1] *= corr0;
            o[dn][2] *= corr1; o[dn][3] *= corr1;
        }

        // ---- probs: ex2 then direct f16x2 pack into A-layout fragments ----
        uint32_t ph[4][4];
        #pragma unroll
        for (int nt = 0; nt < 8; nt++) {
            const float p0 = ex2f(c[nt][0] - mn0), p1 = ex2f(c[nt][1] - mn0);
            const float p2 = ex2f(c[nt][2] - mn1), p3 = ex2f(c[nt][3] - mn1);
            ph[nt >> 1][(nt & 1) * 2 + 0] = cvt_h2(p0, p1);
            ph[nt >> 1][(nt & 1) * 2 + 1] = cvt_h2(p2, p3);
        }

        // ---- row sums via ones-B MMA (no shuffles; consistent with fp16 P) ----
        float csum[4] = {0.f, 0.f, 0.f, 0.f};
        #pragma unroll
        for (int kt = 0; kt < 4; kt++)
            mma16816(csum, ph[kt], ONES2, ONES2);

        // ---- P.V : 2-pass (ph*vh + ph*vl), B-frags via ldmatrix.x4.trans ----
        #pragma unroll
        for (int kt = 0; kt < 4; kt++) {
            #pragma unroll
            for (int dn = 0; dn < 8; dn++) {
                uint32_t vh0, vh1, vl0, vl1;
                ldsm4t(vh0, vh1, vl0, vl1, kb + voff + (uint32_t)(kt * 2304 + dn * 16));
                mma16816(o[dn], ph[kt], vh0, vh1);
                mma16816(o[dn], ph[kt], vl0, vl1);
            }
        }

        lro0 = lro0 * corr0 + csum[0];
        lro1 = lro1 * corr1 + csum[2];
    }

    // ---- epilogue ----
    const float inv0 = 1.f / lro0, inv1 = 1.f / lro1;
    const size_t ob0 = ((size_t)b * SDIM + row0) * (HEADS * HDIM) + h * HDIM;
    const size_t ob1 = ((size_t)b * SDIM + row1) * (HEADS * HDIM) + h * HDIM;
    #pragma unroll
    for (int dn = 0; dn < 8; dn++) {
        float2 r0, r1;
        r0.x = o[dn][0] * inv0; r0.y = o[dn][1] * inv0;
        r1.x = o[dn][2] * inv1; r1.y = o[dn][3] * inv1;
        *(float2*)(outg + ob0 + dn * 8 + 2 * q4) = r0;
        *(float2*)(outg + ob1 + dn * 8 + 2 * q4) = r1;
    }
}

extern "C" void kernel_launch(void* const* d_in, const int* in_sizes, int n_in,
                              void* d_out, int out_size) {
    const float*         q    = (const float*)d_in[0];
    const float*         k    = (const float*)d_in[1];
    const float*         v    = (const float*)d_in[2];
    const float*         bias = (const float*)d_in[3];
    const unsigned char* mask = (const unsigned char*)d_in[4];
    float* out = (float*)d_out;

    detect_mask_kernel<<<1, 32>>>((const unsigned int*)mask);
    prepack_kernel<<<4096, 256>>>(k, v);

    cudaFuncSetAttribute(attn_kernel, cudaFuncAttributeMaxDynamicSharedMemorySize, NSTAGE * BUFB);
    dim3 grid(SDIM / BM, HEADS, 2);
    attn_kernel<<<grid, 256, NSTAGE * BUFB>>>(q, bias, mask, out);
}

// round 13
// speedup vs baseline: 3.1507x; 1.2946x over previous
#include <cuda_runtime.h>
#include <cuda_fp16.h>
#include <cstdint>

#define SDIM 2048
#define HEADS 16
#define HDIM 64
#define BM 64
#define BN 64
#define NTILE (SDIM / BN)
#define RSTR 72        // halfs per padded row
#define ROWB 144       // bytes per padded row
#define PLANE 9216     // 64 rows * 144 B : one plane of one tile
#define BUFB 27648     // 3 planes (KH,KL,VH)
#define NSTAGE 3
#define ONES2 0x3C003C00u   // half2(1.0, 1.0)

__device__ __half g_KH[(size_t)2 * HEADS * SDIM * RSTR];
__device__ __half g_KL[(size_t)2 * HEADS * SDIM * RSTR];
__device__ __half g_VH[(size_t)2 * HEADS * SDIM * RSTR];
__device__ int g_mask_word_mode;

__global__ void detect_mask_kernel(const unsigned int* m) {
    int bad = 0;
    #pragma unroll 8
    for (int i = threadIdx.x; i < 1024; i += 32) {
        const unsigned int w = m[i];
        bad |= (w != 0u && w != 1u && w != 0x3F800000u) ? 1 : 0;
    }
    const unsigned int any = __ballot_sync(0xffffffffu, bad);
    if (threadIdx.x == 0) g_mask_word_mode = (any == 0u) ? 1 : 0;
}

__device__ __forceinline__ uint32_t pack_h2(float x, float y) {
    __half2 h = __floats2half2_rn(x, y);
    return *reinterpret_cast<uint32_t*>(&h);
}
__device__ __forceinline__ void split_h2(float x, float y, uint32_t& hi, uint32_t& lo) {
    const __half hx = __float2half_rn(x), hy = __float2half_rn(y);
    __half2 hp = __halves2half2(hx, hy);
    hi = *reinterpret_cast<uint32_t*>(&hp);
    lo = pack_h2(x - __half2float(hx), y - __half2float(hy));
}
// pack two fp32 into half2 in ONE cvt (lo -> low half, hi -> high half)
__device__ __forceinline__ uint32_t cvt_h2(float lo, float hi) {
    uint32_t d; asm("cvt.rn.f16x2.f32 %0, %1, %2;" : "=r"(d) : "f"(hi), "f"(lo)); return d;
}
__device__ __forceinline__ float ex2f(float x) {
    float r; asm("ex2.approx.f32 %0, %1;" : "=f"(r) : "f"(x)); return r;
}
__device__ __forceinline__ void mma16816(float* c, const uint32_t* a, uint32_t b0, uint32_t b1) {
    asm volatile(
        "mma.sync.aligned.m16n8k16.row.col.f32.f16.f16.f32 "
        "{%0,%1,%2,%3}, {%4,%5,%6,%7}, {%8,%9}, {%0,%1,%2,%3};"
        : "+f"(c[0]), "+f"(c[1]), "+f"(c[2]), "+f"(c[3])
        : "r"(a[0]), "r"(a[1]), "r"(a[2]), "r"(a[3]), "r"(b0), "r"(b1));
}
__device__ __forceinline__ void ldsm4(uint32_t& a, uint32_t& b, uint32_t& c, uint32_t& d, uint32_t addr) {
    asm volatile("ldmatrix.sync.aligned.m8n8.x4.shared.b16 {%0,%1,%2,%3}, [%4];"
                 : "=r"(a), "=r"(b), "=r"(c), "=r"(d) : "r"(addr));
}
__device__ __forceinline__ void ldsm4t(uint32_t& a, uint32_t& b, uint32_t& c, uint32_t& d, uint32_t addr) {
    asm volatile("ldmatrix.sync.aligned.m8n8.x4.trans.shared.b16 {%0,%1,%2,%3}, [%4];"
                 : "=r"(a), "=r"(b), "=r"(c), "=r"(d) : "r"(addr));
}
__device__ __forceinline__ void cpa16(uint32_t dst, const void* src) {
    asm volatile("cp.async.cg.shared.global [%0], [%1], 16;" :: "r"(dst), "l"(src));
}

// ---- one-shot K (hi/lo) + V (hi) fp16 prepack into padded [bh][s][72] planes ----
__global__ __launch_bounds__(256)
void prepack_kernel(const float* __restrict__ kg, const float* __restrict__ vg) {
    const int idx = blockIdx.x * 256 + threadIdx.x;   // B*S*H*16 quads
    const int d4q = idx & 15;
    const int h   = (idx >> 4) & 15;
    const int s   = (idx >> 8) & 2047;
    const int b   = idx >> 19;
    const size_t src = (((size_t)b * SDIM + s) * HEADS + h) * HDIM + d4q * 4;
    const size_t dst = ((size_t)(b * HEADS + h) * SDIM + s) * RSTR + d4q * 4;
    uint32_t h01, l01, h23, l23;
    const float4 kx = *(const float4*)(kg + src);
    split_h2(kx.x, kx.y, h01, l01); split_h2(kx.z, kx.w, h23, l23);
    *(uint32_t*)&g_KH[dst] = h01; *(uint32_t*)&g_KH[dst + 2] = h23;
    *(uint32_t*)&g_KL[dst] = l01; *(uint32_t*)&g_KL[dst + 2] = l23;
    const float4 vx = *(const float4*)(vg + src);
    *(uint32_t*)&g_VH[dst]     = pack_h2(vx.x, vx.y);
    *(uint32_t*)&g_VH[dst + 2] = pack_h2(vx.z, vx.w);
}

__global__ __launch_bounds__(128, 2)
void attn_kernel(const float* __restrict__ qg, const float* __restrict__ biasg,
                 const unsigned char* __restrict__ maskg, float* __restrict__ outg)
{
    extern __shared__ char smem[];
    const uint32_t sbase = (uint32_t)__cvta_generic_to_shared(smem);
    const int tid = threadIdx.x, warp = tid >> 5, lane = tid & 31;
    const int q4 = lane & 3, r8 = lane >> 2;
    const int m0 = blockIdx.x * BM, h = blockIdx.y, b = blockIdx.z;
    const int row0 = m0 + warp * 16 + r8, row1 = row0 + 8;
    const int wordm = g_mask_word_mode;
    const int bh = b * HEADS + h;

    // ldmatrix lane-address components (tl = which 8x8 tile this lane addresses)
    const int tl = lane >> 3, rr = lane & 7;
    // K (non-trans x4): tiles 0,1 = KH k-halves; tiles 2,3 = KL k-halves
    const uint32_t koff = (uint32_t)((tl >> 1) * PLANE + (tl & 1) * 16 + rr * ROWB);
    // V (trans x4): tiles 0,1 = key-halves of d-octet dn; tiles 2,3 = key-halves of dn+1
    const uint32_t voff = (uint32_t)(2 * PLANE + ((tl & 1) * 8 + rr) * ROWB + (tl >> 1) * 16);

    // cp.async chunk coords (128 threads: 12 chunks of 16B each)
    const int ccol = tid & 7, crb = tid >> 3;   // crb in 0..15

    // ---- Q fragments, scaled by 8*log2(e), fp16 hi/lo split ----
    const float QSC = 8.0f * 1.44269504088896341f;
    uint32_t qh[4][4], ql[4][4];
    {
        const size_t qb0 = (((size_t)b * SDIM + row0) * HEADS + h) * HDIM;
        const size_t qb1 = (((size_t)b * SDIM + row1) * HEADS + h) * HDIM;
        #pragma unroll
        for (int dk = 0; dk < 4; dk++) {
            const int c0 = dk * 16 + 2 * q4;
            const float2 x00 = *(const float2*)(qg + qb0 + c0);
            const float2 x10 = *(const float2*)(qg + qb1 + c0);
            const float2 x01 = *(const float2*)(qg + qb0 + c0 + 8);
            const float2 x11 = *(const float2*)(qg + qb1 + c0 + 8);
            split_h2(QSC * x00.x, QSC * x00.y, qh[dk][0], ql[dk][0]);
            split_h2(QSC * x10.x, QSC * x10.y, qh[dk][1], ql[dk][1]);
            split_h2(QSC * x01.x, QSC * x01.y, qh[dk][2], ql[dk][2]);
            split_h2(QSC * x11.x, QSC * x11.y, qh[dk][3], ql[dk][3]);
        }
    }

    float o[8][4];
    #pragma unroll
    for (int i = 0; i < 8; i++) { o[i][0] = o[i][1] = o[i][2] = o[i][3] = 0.f; }
    float mro0 = -1e30f, mro1 = -1e30f, lro0 = 0.f, lro1 = 0.f;

    const size_t biasb0 = (((size_t)b * HEADS + h) * SDIM + row0) * SDIM;
    const size_t biasb1 = (((size_t)b * HEADS + h) * SDIM + row1) * SDIM;
    const size_t maskb0 = ((size_t)b * SDIM + row0) * SDIM;
    const size_t maskb1 = ((size_t)b * SDIM + row1) * SDIM;

    // ---- async tile prefetch: 3 planes x 64 rows x 128B, 12 chunks/thread ----
    #define PREFETCH(T, BUFI) do {                                              \
        const uint32_t dstb_ = sbase + (uint32_t)(BUFI) * BUFB;                 \
        const size_t rowbase_ = (size_t)bh * SDIM + (T) * BN;                   \
        _Pragma("unroll")                                                       \
        for (int i_ = 0; i_ < 12; i_++) {                                       \
            const int plane_ = i_ >> 2;                                         \
            const int r_ = (i_ & 3) * 16 + crb;                                 \
            const size_t so_ = (rowbase_ + r_) * RSTR + ccol * 8;               \
            const __half* sp_ = (plane_ == 0) ? (g_KH + so_)                    \
                              : (plane_ == 1) ? (g_KL + so_) : (g_VH + so_);    \
            cpa16(dstb_ + plane_ * PLANE + r_ * ROWB + ccol * 16, sp_);         \
        }                                                                       \
        asm volatile("cp.async.commit_group;" ::: "memory");                    \
    } while (0)

    PREFETCH(0, 0);
    PREFETCH(1, 1);

    for (int t = 0; t < NTILE; t++) {
        if (t + 1 < NTILE) {
            asm volatile("cp.async.wait_group 1;" ::: "memory");
        } else {
            asm volatile("cp.async.wait_group 0;" ::: "memory");
        }
        __syncthreads();   // single barrier per tile: data ready + all warps done with t-1
        if (t + 2 < NTILE) PREFETCH(t + 2, (t + 2) % NSTAGE);

        const uint32_t kb = sbase + (uint32_t)(t % NSTAGE) * BUFB;
        const int n0 = t * BN;

        // ---- issue this tile's bias+mask loads FIRST (latency hidden under QK MMAs) ----
        float2 bb0a[8], bb1a[8];
        int2   m0a[8], m1a[8];
        #pragma unroll
        for (int nt = 0; nt < 8; nt++) {
            const int col = n0 + nt * 8 + 2 * q4;
            bb0a[nt] = *(const float2*)(biasg + biasb0 + col);
            bb1a[nt] = *(const float2*)(biasg + biasb1 + col);
            if (wordm) {
                m0a[nt] = *(const int2*)((const int*)maskg + maskb0 + col);
                m1a[nt] = *(const int2*)((const int*)maskg + maskb1 + col);
            } else {
                m0a[nt].x = *(const unsigned short*)(maskg + maskb0 + col);
                m1a[nt].x = *(const unsigned short*)(maskg + maskb1 + col);
                m0a[nt].y = 0; m1a[nt].y = 0;
            }
        }

        // ---- QK^T : 3-pass fp16-split HMMA, B-frags via ldmatrix.x4 ----
        float c[8][4];
        #pragma unroll
        for (int i = 0; i < 8; i++) { c[i][0] = c[i][1] = c[i][2] = c[i][3] = 0.f; }
        #pragma unroll
        for (int dk = 0; dk < 4; dk++) {
            #pragma unroll
            for (int nt = 0; nt < 8; nt++) {
                uint32_t bh0, bh1, bl0, bl1;
                ldsm4(bh0, bh1, bl0, bl1, kb + koff + (uint32_t)(nt * 1152 + dk * 32));
                mma16816(c[nt], qh[dk], bh0, bh1);
                mma16816(c[nt], qh[dk], bl0, bl1);
                mma16816(c[nt], ql[dk], bh0, bh1);
            }
        }

        // ---- bias (x log2e) + mask (masked score := 0 in log2 domain too) ----
        const float L2E = 1.44269504088896341f;
        #pragma unroll
        for (int nt = 0; nt < 8; nt++) {
            int k00, k01, k10, k11;
            if (wordm) {
                k00 = (m0a[nt].x != 0); k01 = (m0a[nt].y != 0);
                k10 = (m1a[nt].x != 0); k11 = (m1a[nt].y != 0);
            } else {
                k00 = (m0a[nt].x & 0xff) != 0; k01 = ((m0a[nt].x >> 8) & 0xff) != 0;
                k10 = (m1a[nt].x & 0xff) != 0; k11 = ((m1a[nt].x >> 8) & 0xff) != 0;
            }
            c[nt][0] = k00 ? 0.f : fmaf(bb0a[nt].x, L2E, c[nt][0]);
            c[nt][1] = k01 ? 0.f : fmaf(bb0a[nt].y, L2E, c[nt][1]);
            c[nt][2] = k10 ? 0.f : fmaf(bb1a[nt].x, L2E, c[nt][2]);
            c[nt][3] = k11 ? 0.f : fmaf(bb1a[nt].y, L2E, c[nt][3]);
        }

        // ---- online softmax in log2 domain (max via shfl; sum via ones-MMA below) ----
        float mx0 = -1e30f, mx1 = -1e30f;
        #pragma unroll
        for (int nt = 0; nt < 8; nt++) {
            mx0 = fmaxf(mx0, fmaxf(c[nt][0], c[nt][1]));
            mx1 = fmaxf(mx1, fmaxf(c[nt][2], c[nt][3]));
        }
        mx0 = fmaxf(mx0, __shfl_xor_sync(0xffffffffu, mx0, 1));
        mx0 = fmaxf(mx0, __shfl_xor_sync(0xffffffffu, mx0, 2));
        mx1 = fmaxf(mx1, __shfl_xor_sync(0xffffffffu, mx1, 1));
        mx1 = fmaxf(mx1, __shfl_xor_sync(0xffffffffu, mx1, 2));
        const float mn0 = fmaxf(mro0, mx0), mn1 = fmaxf(mro1, mx1);
        const float corr0 = ex2f(mro0 - mn0), corr1 = ex2f(mro1 - mn1);
        mro0 = mn0; mro1 = mn1;
        #pragma unroll
        for (int dn = 0; dn < 8; dn++) {
            o[dn][0] *= corr0; o[dn][1] *= corr0;
            o[dn][2] *= corr1; o[dn][3] *= corr1;
        }

        // ---- probs: ex2 then direct f16x2 pack into A-layout fragments ----
        uint32_t ph[4][4];
        #pragma unroll
        for (int nt = 0; nt < 8; nt++) {
            const float p0 = ex2f(c[nt][0] - mn0), p1 = ex2f(c[nt][1] - mn0);
            const float p2 = ex2f(c[nt][2] - mn1), p3 = ex2f(c[nt][3] - mn1);
            ph[nt >> 1][(nt & 1) * 2 + 0] = cvt_h2(p0, p1);
            ph[nt >> 1][(nt & 1) * 2 + 1] = cvt_h2(p2, p3);
        }

        // ---- row sums via ones-B MMA (no shuffles; consistent with fp16 P) ----
        float csum[4] = {0.f, 0.f, 0.f, 0.f};
        #pragma unroll
        for (int kt = 0; kt < 4; kt++)
            mma16816(csum, ph[kt], ONES2, ONES2);

        // ---- P.V : single-pass ph*vh; one ldsm4t feeds TWO d-octets ----
        #pragma unroll
        for (int kt = 0; kt < 4; kt++) {
            #pragma unroll
            for (int dnp = 0; dnp < 4; dnp++) {
                uint32_t v0, v1, v2, v3;
                ldsm4t(v0, v1, v2, v3, kb + voff + (uint32_t)(kt * 2304 + dnp * 32));
                mma16816(o[2 * dnp],     ph[kt], v0, v1);
                mma16816(o[2 * dnp + 1], ph[kt], v2, v3);
            }
        }

        lro0 = lro0 * corr0 + csum[0];
        lro1 = lro1 * corr1 + csum[2];
    }

    // ---- epilogue ----
    const float inv0 = 1.f / lro0, inv1 = 1.f / lro1;
    const size_t ob0 = ((size_t)b * SDIM + row0) * (HEADS * HDIM) + h * HDIM;
    const size_t ob1 = ((size_t)b * SDIM + row1) * (HEADS * HDIM) + h * HDIM;
    #pragma unroll
    for (int dn = 0; dn < 8; dn++) {
        float2 r0, r1;
        r0.x = o[dn][0] * inv0; r0.y = o[dn][1] * inv0;
        r1.x = o[dn][2] * inv1; r1.y = o[dn][3] * inv1;
        *(float2*)(outg + ob0 + dn * 8 + 2 * q4) = r0;
        *(float2*)(outg + ob1 + dn * 8 + 2 * q4) = r1;
    }
}

extern "C" void kernel_launch(void* const* d_in, const int* in_sizes, int n_in,
                              void* d_out, int out_size) {
    const float*         q    = (const float*)d_in[0];
    const float*         k    = (const float*)d_in[1];
    const float*         v    = (const float*)d_in[2];
    const float*         bias = (const float*)d_in[3];
    const unsigned char* mask = (const unsigned char*)d_in[4];
    float* out = (float*)d_out;

    detect_mask_kernel<<<1, 32>>>((const unsigned int*)mask);
    prepack_kernel<<<4096, 256>>>(k, v);

    cudaFuncSetAttribute(attn_kernel, cudaFuncAttributeMaxDynamicSharedMemorySize, NSTAGE * BUFB);
    dim3 grid(SDIM / BM, HEADS, 2);
    attn_kernel<<<grid, 128, NSTAGE * BUFB>>>(q, bias, mask, out);
}